// round 3
// baseline (speedup 1.0000x reference)
#include <cuda_runtime.h>
#include <cstdint>
#include <cmath>

// Problem shape (fixed by the dataset):
//   x  : [B=4, S=2048, H=2048]  -> tokens N = 8192, H = 2048
//   Wg : [I=8192, H=2048]
//   Wu : [I=8192, H=2048]
//   Wd : [H=2048, I=8192]
//   act_channels = 2048 (top-k over I per token)
//   out: [N, H] fp32
#define NTOK 8192
#define HDIM 2048
#define IDIM 8192
#define KSEL 2048

// Scratch (device globals: allocation inside kernel_launch is forbidden).
__device__ float g_gate[(size_t)NTOK * IDIM]; // gate logits
__device__ float g_act [(size_t)NTOK * IDIM]; // up projection v, then scaled (in place)

// ---------------------------------------------------------------------------
// SGEMM:  C[m][n] = sum_k A[m][k] * B[n][k]
// A: [M,K] row-major, B: [N,K] row-major, C: [M,N] row-major.
// Tiles: BM=BN=128, BK=16, 256 threads, 8x8 per-thread microtile.
// All dims divisible by tile sizes for this problem -> no bounds checks.
// ---------------------------------------------------------------------------
#define BM 128
#define BN 128
#define BK 16
#define TM 8
#define TN 8

__global__ __launch_bounds__(256, 2)
void sgemm_tt(const float* __restrict__ A,
              const float* __restrict__ B,
              float* __restrict__ C,
              int M, int N, int K)
{
    __shared__ float As[BK][BM + 4];
    __shared__ float Bs[BK][BN + 4];

    const int bm = blockIdx.y * BM;
    const int bn = blockIdx.x * BN;
    const int tid = threadIdx.x;
    const int tx = tid % 16;      // column group
    const int ty = tid / 16;      // row group

    float acc[TM][TN];
#pragma unroll
    for (int i = 0; i < TM; i++)
#pragma unroll
        for (int j = 0; j < TN; j++) acc[i][j] = 0.f;

    const int lr = tid >> 2;            // 0..63
    const int lc = (tid & 3) * 4;       // 0,4,8,12

    for (int k0 = 0; k0 < K; k0 += BK) {
        // Load A tile (128x16), store transposed As[k][m]
#pragma unroll
        for (int l = 0; l < 2; l++) {
            int r = lr + l * 64;
            float4 v = *(const float4*)(A + (size_t)(bm + r) * K + k0 + lc);
            As[lc + 0][r] = v.x; As[lc + 1][r] = v.y;
            As[lc + 2][r] = v.z; As[lc + 3][r] = v.w;
        }
        // Load B tile (128x16), store transposed Bs[k][n]
#pragma unroll
        for (int l = 0; l < 2; l++) {
            int r = lr + l * 64;
            float4 v = *(const float4*)(B + (size_t)(bn + r) * K + k0 + lc);
            Bs[lc + 0][r] = v.x; Bs[lc + 1][r] = v.y;
            Bs[lc + 2][r] = v.z; Bs[lc + 3][r] = v.w;
        }
        __syncthreads();

#pragma unroll
        for (int k = 0; k < BK; k++) {
            float a[TM], b[TN];
#pragma unroll
            for (int i = 0; i < TM; i++) a[i] = As[k][ty * TM + i];
#pragma unroll
            for (int j = 0; j < TN; j++) b[j] = Bs[k][tx * TN + j];
#pragma unroll
            for (int i = 0; i < TM; i++)
#pragma unroll
                for (int j = 0; j < TN; j++)
                    acc[i][j] = fmaf(a[i], b[j], acc[i][j]);
        }
        __syncthreads();
    }

#pragma unroll
    for (int i = 0; i < TM; i++) {
#pragma unroll
        for (int j = 0; j < TN; j += 4) {
            float4 v = make_float4(acc[i][j], acc[i][j + 1], acc[i][j + 2], acc[i][j + 3]);
            *(float4*)(C + (size_t)(bm + ty * TM + i) * N + bn + tx * TN + j) = v;
        }
    }
}

// ---------------------------------------------------------------------------
// Per-token top-K select + silu(gate)*v scatter (in place over v).
// One CTA (256 threads) per token row. Exact k-th-largest via 4-pass 8-bit
// radix select on the order-preserving uint mapping of float.
// ---------------------------------------------------------------------------
__global__ __launch_bounds__(256)
void topk_select_kernel(const float* __restrict__ gate, float* __restrict__ act)
{
    __shared__ unsigned s_u[IDIM];      // 32 KB: sortable keys for this row
    __shared__ int      hist[256];
    __shared__ unsigned s_prefix;
    __shared__ int      s_kk;
    __shared__ int      s_adm;

    const int row = blockIdx.x;
    const int tid = threadIdx.x;
    const float* grow = gate + (size_t)row * IDIM;
    float*       arow = act  + (size_t)row * IDIM;

    // Map float -> order-preserving unsigned key.
    for (int i = tid; i < IDIM; i += 256) {
        unsigned b = __float_as_uint(grow[i]);
        s_u[i] = (b & 0x80000000u) ? ~b : (b | 0x80000000u);
    }
    if (tid == 0) { s_prefix = 0u; s_kk = KSEL; s_adm = 0; }
    __syncthreads();

    // 4-pass MSB radix select for the KSEL-th largest key.
#pragma unroll
    for (int pass = 0; pass < 4; pass++) {
        const int shift = 24 - 8 * pass;
        hist[tid] = 0;
        __syncthreads();
        const unsigned prefix = s_prefix;
        const unsigned himask = (pass == 0) ? 0u : (0xFFFFFFFFu << (shift + 8));
        for (int i = tid; i < IDIM; i += 256) {
            unsigned u = s_u[i];
            if ((u & himask) == prefix)
                atomicAdd(&hist[(u >> shift) & 255], 1);
        }
        __syncthreads();
        if (tid == 0) {
            int kk = s_kk, cum = 0, b = 0;
            for (int x = 255; x >= 0; x--) {
                cum += hist[x];
                if (cum >= kk) { b = x; break; }
            }
            s_kk = kk - (cum - hist[b]);          // rank within the equal group
            s_prefix = prefix | ((unsigned)b << shift);
        }
        __syncthreads();
    }

    const unsigned t = s_prefix;   // exact bit pattern of the KSEL-th largest key
    const int eq_quota = s_kk;     // how many keys == t to admit
    __syncthreads();

    // Select & fuse: scaled = silu(gate) * v for selected channels, else 0.
    for (int i = tid; i < IDIM; i += 256) {
        const unsigned u = s_u[i];
        bool sel = (u > t);
        if (u == t) {
            if (atomicAdd(&s_adm, 1) < eq_quota) sel = true;
        }
        float o = 0.f;
        if (sel) {
            unsigned b = (u & 0x80000000u) ? (u & 0x7FFFFFFFu) : ~u;
            float g = __uint_as_float(b);
            float s = g / (1.f + expf(-g));       // silu
            o = s * arow[i];
        }
        arow[i] = o;
    }
}

// ---------------------------------------------------------------------------
extern "C" void kernel_launch(void* const* d_in, const int* in_sizes, int n_in,
                              void* d_out, int out_size)
{
    const float* x  = (const float*)d_in[0];   // [NTOK, HDIM]
    const float* Wg = (const float*)d_in[1];   // [IDIM, HDIM]
    const float* Wu = (const float*)d_in[2];   // [IDIM, HDIM]
    const float* Wd = (const float*)d_in[3];   // [HDIM, IDIM]
    float* out = (float*)d_out;                // [NTOK, HDIM]

    float* gate = nullptr;
    float* act  = nullptr;
    cudaGetSymbolAddress((void**)&gate, g_gate);
    cudaGetSymbolAddress((void**)&act,  g_act);

    dim3 block(256);

    // GEMM1a: gate = x @ Wg^T   [NTOK, IDIM], K = HDIM
    {
        dim3 grid(IDIM / BN, NTOK / BM);
        sgemm_tt<<<grid, block>>>(x, Wg, gate, NTOK, IDIM, HDIM);
    }
    // GEMM1b: v = x @ Wu^T
    {
        dim3 grid(IDIM / BN, NTOK / BM);
        sgemm_tt<<<grid, block>>>(x, Wu, act, NTOK, IDIM, HDIM);
    }
    // Top-K select + silu*v (act becomes the scaled/scattered tensor)
    {
        topk_select_kernel<<<NTOK, block>>>(gate, act);
    }
    // GEMM2: out = scaled @ Wd^T   [NTOK, HDIM], K = IDIM
    {
        dim3 grid(HDIM / BN, NTOK / BM);
        sgemm_tt<<<grid, block>>>(act, Wd, out, NTOK, HDIM, IDIM);
    }
}

// round 6
// speedup vs baseline: 1.8998x; 1.8998x over previous
#include <cuda_runtime.h>
#include <cuda_bf16.h>
#include <cstdint>
#include <cmath>

#define NTOK 8192
#define HDIM 2048
#define IDIM 8192
#define KSEL 2048

typedef __nv_bfloat16 bf16;

__device__ float g_gate[(size_t)NTOK * IDIM];
__device__ float g_v   [(size_t)NTOK * IDIM];
__device__ bf16 g_xs [3 * (size_t)NTOK * HDIM];
__device__ bf16 g_wgs[3 * (size_t)IDIM * HDIM];
__device__ bf16 g_wus[2 * (size_t)IDIM * HDIM];
__device__ bf16 g_wds[2 * (size_t)HDIM * IDIM];
__device__ bf16 g_as [2 * (size_t)NTOK * IDIM];

__device__ __forceinline__ uint32_t smem_u32(const void* p) {
    uint32_t a;
    asm("{ .reg .u64 t; cvta.to.shared.u64 t, %1; cvt.u32.u64 %0, t; }" : "=r"(a) : "l"(p));
    return a;
}
#define CP16(d, s)  asm volatile("cp.async.cg.shared.global [%0], [%1], 16;" :: "r"(d), "l"(s) : "memory")
#define CP_COMMIT() asm volatile("cp.async.commit_group;" ::: "memory")
#define CP_WAIT(n)  asm volatile("cp.async.wait_group %0;" :: "n"(n) : "memory")
#define LDM4(r0, r1, r2, r3, a) \
    asm volatile("ldmatrix.sync.aligned.m8n8.x4.shared.b16 {%0,%1,%2,%3}, [%4];" \
                 : "=r"(r0), "=r"(r1), "=r"(r2), "=r"(r3) : "r"(a))
#define MMA16816(c0, c1, c2, c3, a0, a1, a2, a3, b0, b1) \
    asm volatile("mma.sync.aligned.m16n8k16.row.col.f32.bf16.bf16.f32 " \
                 "{%0,%1,%2,%3},{%4,%5,%6,%7},{%8,%9},{%0,%1,%2,%3};" \
                 : "+f"(c0), "+f"(c1), "+f"(c2), "+f"(c3) \
                 : "r"(a0), "r"(a1), "r"(a2), "r"(a3), "r"(b0), "r"(b1))

// ---------------------------------------------------------------------------
// Split bf16 GEMM via mma.sync:
//   C[m][n] = sum over pairs p: A_plane(wa_p)[m,:] . B_plane(wb_p)[n,:]
// A planes: [M,K] bf16 row-major; B planes: [N,K] bf16 row-major; C fp32 [M,N].
// CTA tile 256x128, 512 threads (16 warps, 4x4), warp tile 64x32.
// K-chunk 64 per stage (128B rows, SW128-style XOR swizzle), 3-stage cp.async.
// ---------------------------------------------------------------------------
#define BM 256
#define BN 128
#define STAGEB 49152       // 32768 (A) + 16384 (B)
#define SMEMSZ (3 * STAGEB)

__device__ __forceinline__ void hload(uint32_t st,
    const bf16* __restrict__ A, const bf16* __restrict__ B,
    int bm, int bn, int K, size_t plA, size_t plB,
    uint32_t wa, uint32_t wb, int t, int CH, int tid)
{
    const int p = t / CH;
    const int k0 = (t - p * CH) * 64;
    const bf16* Ab = A + (size_t)((wa >> (4 * p)) & 15u) * plA + k0;
    const bf16* Bb = B + (size_t)((wb >> (4 * p)) & 15u) * plB + k0;
#pragma unroll
    for (int i = 0; i < 4; i++) {                       // A: 2048 16B chunks
        int idx = tid + i * 512;
        int r = idx >> 3, c8 = idx & 7;
        CP16(st + (uint32_t)((r * 128 + c8 * 16) ^ ((r & 7) << 4)),
             Ab + (size_t)(bm + r) * K + c8 * 8);
    }
#pragma unroll
    for (int i = 0; i < 2; i++) {                       // B: 1024 16B chunks
        int idx = tid + i * 512;
        int r = idx >> 3, c8 = idx & 7;
        CP16(st + 32768u + (uint32_t)((r * 128 + c8 * 16) ^ ((r & 7) << 4)),
             Bb + (size_t)(bn + r) * K + c8 * 8);
    }
    CP_COMMIT();
}

__global__ __launch_bounds__(512, 1)
void hgemm(const bf16* __restrict__ A, const bf16* __restrict__ B,
           float* __restrict__ C, int N, int K, size_t plA, size_t plB,
           uint32_t wa, uint32_t wb, int NP)
{
    extern __shared__ char smem[];
    const uint32_t sb = smem_u32(smem);
    const int tid = threadIdx.x, wid = tid >> 5, lane = tid & 31;
    const int bm = blockIdx.y * BM, bn = blockIdx.x * BN;
    const int wm = (wid >> 2) * 64, wn = (wid & 3) * 32;
    const int CH = K >> 6;
    const int TOT = NP * CH;

    float c[4][4][4];
#pragma unroll
    for (int i = 0; i < 4; i++)
#pragma unroll
        for (int j = 0; j < 4; j++)
#pragma unroll
            for (int q = 0; q < 4; q++) c[i][j][q] = 0.f;

    hload(sb, A, B, bm, bn, K, plA, plB, wa, wb, 0, CH, tid);
    hload(sb + STAGEB, A, B, bm, bn, K, plA, plB, wa, wb, 1, CH, tid);

    // Per-lane ldmatrix row/chunk decomposition (constant across stages)
    const int a_mrow = lane & 15;          // m row within 16
    const int a_kc   = lane >> 4;          // 16B chunk within k16
    const int b_nrow = (lane & 7) + ((lane >> 4) << 3);
    const int b_kc   = (lane >> 3) & 1;

    for (int t = 0; t < TOT; t++) {
        const uint32_t st = sb + (uint32_t)(t % 3) * STAGEB;
        CP_WAIT(1);
        __syncthreads();
        if (t + 2 < TOT)
            hload(sb + (uint32_t)((t + 2) % 3) * STAGEB, A, B, bm, bn, K,
                  plA, plB, wa, wb, t + 2, CH, tid);
        else
            CP_COMMIT();

#pragma unroll
        for (int kk = 0; kk < 4; kk++) {
            uint32_t a[4][4], b[2][4];
#pragma unroll
            for (int mt = 0; mt < 4; mt++) {
                int r = wm + mt * 16 + a_mrow;
                int ch = kk * 2 + a_kc;
                uint32_t ad = st + (uint32_t)((r * 128 + ch * 16) ^ ((r & 7) << 4));
                LDM4(a[mt][0], a[mt][1], a[mt][2], a[mt][3], ad);
            }
#pragma unroll
            for (int nt = 0; nt < 2; nt++) {
                int r = wn + nt * 16 + b_nrow;
                int ch = kk * 2 + b_kc;
                uint32_t ad = st + 32768u + (uint32_t)((r * 128 + ch * 16) ^ ((r & 7) << 4));
                LDM4(b[nt][0], b[nt][1], b[nt][2], b[nt][3], ad);
            }
#pragma unroll
            for (int mt = 0; mt < 4; mt++)
#pragma unroll
                for (int j = 0; j < 4; j++)
                    MMA16816(c[mt][j][0], c[mt][j][1], c[mt][j][2], c[mt][j][3],
                             a[mt][0], a[mt][1], a[mt][2], a[mt][3],
                             b[j >> 1][(j & 1) * 2], b[j >> 1][(j & 1) * 2 + 1]);
        }
    }

    // Epilogue: c0,c1 -> (row, col..col+1); c2,c3 -> (row+8, ...)
#pragma unroll
    for (int mt = 0; mt < 4; mt++) {
        int row = bm + wm + mt * 16 + (lane >> 2);
#pragma unroll
        for (int j = 0; j < 4; j++) {
            int col = bn + wn + j * 8 + (lane & 3) * 2;
            *(float2*)(C + (size_t)row * N + col)       = make_float2(c[mt][j][0], c[mt][j][1]);
            *(float2*)(C + (size_t)(row + 8) * N + col) = make_float2(c[mt][j][2], c[mt][j][3]);
        }
    }
}

// ---------------------------------------------------------------------------
__global__ void split3_kernel(const float* __restrict__ a, bf16* __restrict__ o, size_t n)
{
    size_t i = (size_t)blockIdx.x * blockDim.x + threadIdx.x;
    for (; i < n; i += (size_t)gridDim.x * blockDim.x) {
        float x = a[i];
        bf16 h = __float2bfloat16(x);
        float r1 = x - __bfloat162float(h);
        bf16 m = __float2bfloat16(r1);
        o[i] = h; o[n + i] = m; o[2 * n + i] = __float2bfloat16(r1 - __bfloat162float(m));
    }
}
__global__ void split2_kernel(const float* __restrict__ a, bf16* __restrict__ o, size_t n)
{
    size_t i = (size_t)blockIdx.x * blockDim.x + threadIdx.x;
    for (; i < n; i += (size_t)gridDim.x * blockDim.x) {
        float x = a[i];
        bf16 h = __float2bfloat16(x);
        o[i] = h; o[n + i] = __float2bfloat16(x - __bfloat162float(h));
    }
}

// Per-token exact top-K (radix select) + silu(gate)*v, output as 2-way bf16 split
__global__ __launch_bounds__(256)
void topk_kernel(const float* __restrict__ gate, const float* __restrict__ v,
                 bf16* __restrict__ ah, bf16* __restrict__ am)
{
    __shared__ unsigned s_u[IDIM];
    __shared__ int hist[256];
    __shared__ unsigned s_prefix;
    __shared__ int s_kk, s_adm;

    const int row = blockIdx.x, tid = threadIdx.x;
    const float* grow = gate + (size_t)row * IDIM;
    const float* vrow = v + (size_t)row * IDIM;

    for (int i = tid; i < IDIM; i += 256) {
        unsigned b = __float_as_uint(grow[i]);
        s_u[i] = (b & 0x80000000u) ? ~b : (b | 0x80000000u);
    }
    if (tid == 0) { s_prefix = 0u; s_kk = KSEL; s_adm = 0; }
    __syncthreads();
#pragma unroll
    for (int pass = 0; pass < 4; pass++) {
        const int shift = 24 - 8 * pass;
        hist[tid] = 0;
        __syncthreads();
        const unsigned prefix = s_prefix;
        const unsigned himask = (pass == 0) ? 0u : (0xFFFFFFFFu << (shift + 8));
        for (int i = tid; i < IDIM; i += 256) {
            unsigned u = s_u[i];
            if ((u & himask) == prefix) atomicAdd(&hist[(u >> shift) & 255], 1);
        }
        __syncthreads();
        if (tid == 0) {
            int kk = s_kk, cum = 0, b = 0;
            for (int x = 255; x >= 0; x--) { cum += hist[x]; if (cum >= kk) { b = x; break; } }
            s_kk = kk - (cum - hist[b]);
            s_prefix = prefix | ((unsigned)b << shift);
        }
        __syncthreads();
    }
    const unsigned t = s_prefix;
    const int eq_quota = s_kk;
    __syncthreads();

    for (int i = tid; i < IDIM; i += 256) {
        const unsigned u = s_u[i];
        bool sel = (u > t);
        if (u == t) { if (atomicAdd(&s_adm, 1) < eq_quota) sel = true; }
        float o = 0.f;
        if (sel) {
            unsigned b = (u & 0x80000000u) ? (u & 0x7FFFFFFFu) : ~u;
            float g = __uint_as_float(b);
            o = (g / (1.f + expf(-g))) * vrow[i];
        }
        const size_t idx = (size_t)row * IDIM + i;
        bf16 h = __float2bfloat16(o);
        ah[idx] = h;
        am[idx] = __float2bfloat16(o - __bfloat162float(h));
    }
}

// ---------------------------------------------------------------------------
extern "C" void kernel_launch(void* const* d_in, const int* in_sizes, int n_in,
                              void* d_out, int out_size)
{
    const float* x  = (const float*)d_in[0];
    const float* Wg = (const float*)d_in[1];
    const float* Wu = (const float*)d_in[2];
    const float* Wd = (const float*)d_in[3];
    float* out = (float*)d_out;

    float *gate, *vv;
    bf16 *xs, *wgs, *wus, *wds, *as;
    cudaGetSymbolAddress((void**)&gate, g_gate);
    cudaGetSymbolAddress((void**)&vv, g_v);
    cudaGetSymbolAddress((void**)&xs, g_xs);
    cudaGetSymbolAddress((void**)&wgs, g_wgs);
    cudaGetSymbolAddress((void**)&wus, g_wus);
    cudaGetSymbolAddress((void**)&wds, g_wds);
    cudaGetSymbolAddress((void**)&as, g_as);

    const size_t nx = (size_t)NTOK * HDIM;
    const size_t nw = (size_t)IDIM * HDIM;
    const size_t na = (size_t)NTOK * IDIM;

    cudaFuncSetAttribute(hgemm, cudaFuncAttributeMaxDynamicSharedMemorySize, SMEMSZ);

    split3_kernel<<<2048, 256>>>(x, xs, nx);
    split3_kernel<<<2048, 256>>>(Wg, wgs, nw);
    split2_kernel<<<2048, 256>>>(Wu, wus, nw);
    split2_kernel<<<2048, 256>>>(Wd, wds, nw);

    // pair encodings, 4 bits/pair (LSB first)
    const uint32_t gA = 0x201100u, gB = 0x021010u;   // (h,h)(h,m)(m,h)(m,m)(h,l)(l,h)
    const uint32_t sA = 0x100u,    sB = 0x010u;      // (h,h)(h,m)(m,h)

    // gate = x @ Wg^T : M=8192, N=8192, K=2048
    hgemm<<<dim3(IDIM / BN, NTOK / BM), 512, SMEMSZ>>>(
        xs, wgs, gate, IDIM, HDIM, nx, nw, gA, gB, 6);
    // v = x @ Wu^T (planes 0,1 of xs)
    hgemm<<<dim3(IDIM / BN, NTOK / BM), 512, SMEMSZ>>>(
        xs, wus, vv, IDIM, HDIM, nx, nw, sA, sB, 3);
    // top-k + silu*v -> 2-way split activation
    topk_kernel<<<NTOK, 256>>>(gate, vv, as, as + na);
    // out = act @ Wd^T : M=8192, N=2048, K=8192
    hgemm<<<dim3(HDIM / BN, NTOK / BM), 512, SMEMSZ>>>(
        as, wds, out, HDIM, IDIM, na, nw, sA, sB, 3);
}

// round 7
// speedup vs baseline: 2.4936x; 1.3126x over previous
#include <cuda_runtime.h>
#include <cuda_fp16.h>
#include <cstdint>
#include <cmath>

#define NTOK 8192
#define HDIM 2048
#define IDIM 8192
#define KSEL 2048

// Scratch (device globals; allocation in kernel_launch is forbidden)
__device__ float g_gate[(size_t)NTOK * IDIM];
__device__ float g_v   [(size_t)NTOK * IDIM];
__device__ __half g_xs [2 * (size_t)NTOK * HDIM];   // x 2-split (unscaled)
__device__ __half g_wgs[2 * (size_t)IDIM * HDIM];   // 32*Wg 2-split
__device__ __half g_wus[2 * (size_t)IDIM * HDIM];   // 32*Wu 2-split
__device__ __half g_wds[2 * (size_t)HDIM * IDIM];   // 32*Wd 2-split
__device__ __half g_as [2 * (size_t)NTOK * IDIM];   // scaled activation 2-split

__device__ __forceinline__ uint32_t smem_u32(const void* p) {
    uint32_t a;
    asm("{ .reg .u64 t; cvta.to.shared.u64 t, %1; cvt.u32.u64 %0, t; }" : "=r"(a) : "l"(p));
    return a;
}
#define CP16(d, s)  asm volatile("cp.async.cg.shared.global [%0], [%1], 16;" :: "r"(d), "l"(s) : "memory")
#define CP_COMMIT() asm volatile("cp.async.commit_group;" ::: "memory")
#define CP_WAIT(n)  asm volatile("cp.async.wait_group %0;" :: "n"(n) : "memory")
#define LDM4(r0, r1, r2, r3, a) \
    asm volatile("ldmatrix.sync.aligned.m8n8.x4.shared.b16 {%0,%1,%2,%3}, [%4];" \
                 : "=r"(r0), "=r"(r1), "=r"(r2), "=r"(r3) : "r"(a))
#define MMA16816(c0, c1, c2, c3, a0, a1, a2, a3, b0, b1) \
    asm volatile("mma.sync.aligned.m16n8k16.row.col.f32.f16.f16.f32 " \
                 "{%0,%1,%2,%3},{%4,%5,%6,%7},{%8,%9},{%0,%1,%2,%3};" \
                 : "+f"(c0), "+f"(c1), "+f"(c2), "+f"(c3) \
                 : "r"(a0), "r"(a1), "r"(a2), "r"(a3), "r"(b0), "r"(b1))

// ---------------------------------------------------------------------------
// Split fp16 GEMM: C[m][n] = alpha * sum_pairs A_plane[m,:] . B_plane[n,:]
// A planes [M,K], B planes [N,K] fp16 row-major; C fp32 [M,N].
// CTA tile 128x256, 256 threads (8 warps 2x4), warp tile 64x64.
// K-chunk 64 (128B rows, XOR swizzle), 3-stage cp.async pipeline.
// ---------------------------------------------------------------------------
#define BM 128
#define BN 256
#define STAGEB 49152            // A 16KB + B 32KB
#define SMEMSZ (3 * STAGEB)

__device__ __forceinline__ void hload(uint32_t st,
    const __half* __restrict__ A, const __half* __restrict__ B,
    int bm, int bn, int K, size_t plA, size_t plB,
    uint32_t wa, uint32_t wb, int t, int CH, int tid)
{
    const int p = t / CH;
    const int k0 = (t - p * CH) * 64;
    const __half* Ab = A + (size_t)((wa >> (4 * p)) & 15u) * plA + k0;
    const __half* Bb = B + (size_t)((wb >> (4 * p)) & 15u) * plB + k0;
#pragma unroll
    for (int i = 0; i < 4; i++) {                   // A: 1024 16B chunks
        int idx = tid + i * 256;
        int r = idx >> 3, c8 = idx & 7;
        CP16(st + (uint32_t)((r * 128 + c8 * 16) ^ ((r & 7) << 4)),
             Ab + (size_t)(bm + r) * K + c8 * 8);
    }
#pragma unroll
    for (int i = 0; i < 8; i++) {                   // B: 2048 16B chunks
        int idx = tid + i * 256;
        int r = idx >> 3, c8 = idx & 7;
        CP16(st + 16384u + (uint32_t)((r * 128 + c8 * 16) ^ ((r & 7) << 4)),
             Bb + (size_t)(bn + r) * K + c8 * 8);
    }
    CP_COMMIT();
}

__global__ __launch_bounds__(256, 1)
void hgemm(const __half* __restrict__ A, const __half* __restrict__ B,
           float* __restrict__ C, int N, int K, size_t plA, size_t plB,
           uint32_t wa, uint32_t wb, int NP, float alpha)
{
    extern __shared__ char smem[];
    const uint32_t sb = smem_u32(smem);
    const int tid = threadIdx.x, wid = tid >> 5, lane = tid & 31;
    const int bm = blockIdx.y * BM, bn = blockIdx.x * BN;
    const int wm = (wid >> 2) * 64, wn = (wid & 3) * 64;
    const int CH = K >> 6;
    const int TOT = NP * CH;

    float c[4][8][4];
#pragma unroll
    for (int i = 0; i < 4; i++)
#pragma unroll
        for (int j = 0; j < 8; j++)
#pragma unroll
            for (int q = 0; q < 4; q++) c[i][j][q] = 0.f;

    hload(sb, A, B, bm, bn, K, plA, plB, wa, wb, 0, CH, tid);
    hload(sb + STAGEB, A, B, bm, bn, K, plA, plB, wa, wb, 1, CH, tid);

    const int a_mrow = lane & 15;
    const int a_kc   = lane >> 4;
    const int b_nrow = (lane & 7) + ((lane >> 4) << 3);
    const int b_kc   = (lane >> 3) & 1;

    for (int t = 0; t < TOT; t++) {
        const uint32_t st = sb + (uint32_t)(t % 3) * STAGEB;
        CP_WAIT(1);
        __syncthreads();
        if (t + 2 < TOT)
            hload(sb + (uint32_t)((t + 2) % 3) * STAGEB, A, B, bm, bn, K,
                  plA, plB, wa, wb, t + 2, CH, tid);
        else
            CP_COMMIT();

#pragma unroll
        for (int kk = 0; kk < 4; kk++) {
            uint32_t a[4][4], b[4][4];
#pragma unroll
            for (int mt = 0; mt < 4; mt++) {
                int r = wm + mt * 16 + a_mrow;
                int ch = kk * 2 + a_kc;
                uint32_t ad = st + (uint32_t)((r * 128 + ch * 16) ^ ((r & 7) << 4));
                LDM4(a[mt][0], a[mt][1], a[mt][2], a[mt][3], ad);
            }
#pragma unroll
            for (int nt = 0; nt < 4; nt++) {
                int r = wn + nt * 16 + b_nrow;
                int ch = kk * 2 + b_kc;
                uint32_t ad = st + 16384u + (uint32_t)((r * 128 + ch * 16) ^ ((r & 7) << 4));
                LDM4(b[nt][0], b[nt][1], b[nt][2], b[nt][3], ad);
            }
#pragma unroll
            for (int mt = 0; mt < 4; mt++)
#pragma unroll
                for (int j = 0; j < 8; j++)
                    MMA16816(c[mt][j][0], c[mt][j][1], c[mt][j][2], c[mt][j][3],
                             a[mt][0], a[mt][1], a[mt][2], a[mt][3],
                             b[j >> 1][(j & 1) * 2], b[j >> 1][(j & 1) * 2 + 1]);
        }
    }

#pragma unroll
    for (int mt = 0; mt < 4; mt++) {
        int row = bm + wm + mt * 16 + (lane >> 2);
#pragma unroll
        for (int j = 0; j < 8; j++) {
            int col = bn + wn + j * 8 + (lane & 3) * 2;
            *(float2*)(C + (size_t)row * N + col) =
                make_float2(alpha * c[mt][j][0], alpha * c[mt][j][1]);
            *(float2*)(C + (size_t)(row + 8) * N + col) =
                make_float2(alpha * c[mt][j][2], alpha * c[mt][j][3]);
        }
    }
}

// ---------------------------------------------------------------------------
// fp16 2-way split with pre-scale (scale is a power of 2; undone via alpha)
__global__ void split2h(const float* __restrict__ a, __half* __restrict__ o,
                        size_t n, float scale)
{
    size_t i = (size_t)blockIdx.x * blockDim.x + threadIdx.x;
    for (; i < n; i += (size_t)gridDim.x * blockDim.x) {
        float x = a[i] * scale;
        __half h = __float2half_rn(x);
        o[i] = h;
        o[n + i] = __float2half_rn(x - __half2float(h));
    }
}

// Per-token exact top-K (4-pass radix select) + silu(gate)*v,
// emitted as an fp16 2-way split (input of the down GEMM).
__global__ __launch_bounds__(256)
void topk_kernel(const float* __restrict__ gate, const float* __restrict__ v,
                 __half* __restrict__ ah, __half* __restrict__ am)
{
    __shared__ unsigned s_u[IDIM];
    __shared__ int hist[256];
    __shared__ unsigned s_prefix;
    __shared__ int s_kk, s_adm;

    const int row = blockIdx.x, tid = threadIdx.x;
    const float* grow = gate + (size_t)row * IDIM;
    const float* vrow = v + (size_t)row * IDIM;

    for (int i = tid; i < IDIM; i += 256) {
        unsigned b = __float_as_uint(grow[i]);
        s_u[i] = (b & 0x80000000u) ? ~b : (b | 0x80000000u);
    }
    if (tid == 0) { s_prefix = 0u; s_kk = KSEL; s_adm = 0; }
    __syncthreads();
#pragma unroll
    for (int pass = 0; pass < 4; pass++) {
        const int shift = 24 - 8 * pass;
        hist[tid] = 0;
        __syncthreads();
        const unsigned prefix = s_prefix;
        const unsigned himask = (pass == 0) ? 0u : (0xFFFFFFFFu << (shift + 8));
        for (int i = tid; i < IDIM; i += 256) {
            unsigned u = s_u[i];
            if ((u & himask) == prefix) atomicAdd(&hist[(u >> shift) & 255], 1);
        }
        __syncthreads();
        if (tid == 0) {
            int kk = s_kk, cum = 0, b = 0;
            for (int x = 255; x >= 0; x--) { cum += hist[x]; if (cum >= kk) { b = x; break; } }
            s_kk = kk - (cum - hist[b]);
            s_prefix = prefix | ((unsigned)b << shift);
        }
        __syncthreads();
    }
    const unsigned t = s_prefix;
    const int eq_quota = s_kk;
    __syncthreads();

    for (int i = tid; i < IDIM; i += 256) {
        const unsigned u = s_u[i];
        bool sel = (u > t);
        if (u == t) { if (atomicAdd(&s_adm, 1) < eq_quota) sel = true; }
        float o = 0.f;
        if (sel) {
            unsigned b = (u & 0x80000000u) ? (u & 0x7FFFFFFFu) : ~u;
            float g = __uint_as_float(b);
            o = (g / (1.f + expf(-g))) * vrow[i];
        }
        const size_t idx = (size_t)row * IDIM + i;
        __half h = __float2half_rn(o);
        ah[idx] = h;
        am[idx] = __float2half_rn(o - __half2float(h));
    }
}

// ---------------------------------------------------------------------------
extern "C" void kernel_launch(void* const* d_in, const int* in_sizes, int n_in,
                              void* d_out, int out_size)
{
    const float* x  = (const float*)d_in[0];
    const float* Wg = (const float*)d_in[1];
    const float* Wu = (const float*)d_in[2];
    const float* Wd = (const float*)d_in[3];
    float* out = (float*)d_out;

    float *gate, *vv;
    __half *xs, *wgs, *wus, *wds, *as;
    cudaGetSymbolAddress((void**)&gate, g_gate);
    cudaGetSymbolAddress((void**)&vv, g_v);
    cudaGetSymbolAddress((void**)&xs, g_xs);
    cudaGetSymbolAddress((void**)&wgs, g_wgs);
    cudaGetSymbolAddress((void**)&wus, g_wus);
    cudaGetSymbolAddress((void**)&wds, g_wds);
    cudaGetSymbolAddress((void**)&as, g_as);

    const size_t nx = (size_t)NTOK * HDIM;
    const size_t nw = (size_t)IDIM * HDIM;
    const size_t na = (size_t)NTOK * IDIM;

    cudaFuncSetAttribute(hgemm, cudaFuncAttributeMaxDynamicSharedMemorySize, SMEMSZ);

    // Splits: weights pre-scaled by 32 (keeps m-plane out of fp16 denormals);
    // undone exactly by alpha = 1/32 in the GEMM epilogue.
    split2h<<<2048, 256>>>(x,  xs,  nx, 1.0f);
    split2h<<<2048, 256>>>(Wg, wgs, nw, 32.0f);
    split2h<<<2048, 256>>>(Wu, wus, nw, 32.0f);
    split2h<<<2048, 256>>>(Wd, wds, nw, 32.0f);

    // pair encoding, 4 bits/pair LSB-first: (h,h)(h,m)(m,h)
    const uint32_t sA = 0x100u, sB = 0x010u;
    const float alpha = 1.0f / 32.0f;

    // gate = x @ Wg^T : M=8192, N=8192, K=2048
    hgemm<<<dim3(IDIM / BN, NTOK / BM), 256, SMEMSZ>>>(
        xs, wgs, gate, IDIM, HDIM, nx, nw, sA, sB, 3, alpha);
    // v = x @ Wu^T
    hgemm<<<dim3(IDIM / BN, NTOK / BM), 256, SMEMSZ>>>(
        xs, wus, vv, IDIM, HDIM, nx, nw, sA, sB, 3, alpha);
    // top-k + silu*v -> fp16 2-way split activation (unscaled)
    topk_kernel<<<NTOK, 256>>>(gate, vv, as, as + na);
    // out = act @ Wd^T : M=8192, N=2048, K=8192
    hgemm<<<dim3(HDIM / BN, NTOK / BM), 256, SMEMSZ>>>(
        as, wds, out, HDIM, IDIM, na, nw, sA, sB, 3, alpha);
}

// round 8
// speedup vs baseline: 3.2764x; 1.3139x over previous
#include <cuda_runtime.h>
#include <cuda_fp16.h>
#include <cstdint>
#include <cmath>

#define NTOK 8192
#define HDIM 2048
#define IDIM 8192
#define KSEL 2048

__device__ float g_gate[(size_t)NTOK * IDIM];
__device__ float g_v   [(size_t)NTOK * IDIM];
__device__ __half g_xs [2 * (size_t)NTOK * HDIM];
__device__ __half g_wgs[2 * (size_t)IDIM * HDIM];
__device__ __half g_wus[2 * (size_t)IDIM * HDIM];
__device__ __half g_wds[2 * (size_t)HDIM * IDIM];
__device__ __half g_as [2 * (size_t)NTOK * IDIM];

__device__ __forceinline__ uint32_t smem_u32(const void* p) {
    uint32_t a;
    asm("{ .reg .u64 t; cvta.to.shared.u64 t, %1; cvt.u32.u64 %0, t; }" : "=r"(a) : "l"(p));
    return a;
}
#define CP16(d, s)  asm volatile("cp.async.cg.shared.global [%0], [%1], 16;" :: "r"(d), "l"(s) : "memory")
#define CP_COMMIT() asm volatile("cp.async.commit_group;" ::: "memory")
#define CP_WAIT(n)  asm volatile("cp.async.wait_group %0;" :: "n"(n) : "memory")
#define LDM4(r0, r1, r2, r3, a) \
    asm volatile("ldmatrix.sync.aligned.m8n8.x4.shared.b16 {%0,%1,%2,%3}, [%4];" \
                 : "=r"(r0), "=r"(r1), "=r"(r2), "=r"(r3) : "r"(a))
#define MMA16816(c0, c1, c2, c3, a0, a1, a2, a3, b0, b1) \
    asm volatile("mma.sync.aligned.m16n8k16.row.col.f32.f16.f16.f32 " \
                 "{%0,%1,%2,%3},{%4,%5,%6,%7},{%8,%9},{%0,%1,%2,%3};" \
                 : "+f"(c0), "+f"(c1), "+f"(c2), "+f"(c3) \
                 : "r"(a0), "r"(a1), "r"(a2), "r"(a3), "r"(b0), "r"(b1))

// ---------------------------------------------------------------------------
// Split fp16 GEMM: C = alpha * sum_pairs A_plane . B_plane^T
// CTA tile 128x256, 256 threads (8 warps 2x4), warp tile 64x64.
// K-chunk 64 per stage, 4-stage cp.async, register-double-buffered ldmatrix.
// ---------------------------------------------------------------------------
#define BM 128
#define BN 256
#define STAGEB 49152            // A 16KB + B 32KB
#define NSTG 4
#define SMEMSZ (NSTG * STAGEB)

__device__ __forceinline__ void hload(uint32_t st,
    const __half* __restrict__ A, const __half* __restrict__ B,
    int bm, int bn, int K, size_t plA, size_t plB,
    uint32_t wa, uint32_t wb, int t, int CH, int tid)
{
    const int p = t / CH;
    const int k0 = (t - p * CH) * 64;
    const __half* Ab = A + (size_t)((wa >> (4 * p)) & 15u) * plA + k0;
    const __half* Bb = B + (size_t)((wb >> (4 * p)) & 15u) * plB + k0;
#pragma unroll
    for (int i = 0; i < 4; i++) {
        int idx = tid + i * 256;
        int r = idx >> 3, c8 = idx & 7;
        CP16(st + (uint32_t)((r * 128 + c8 * 16) ^ ((r & 7) << 4)),
             Ab + (size_t)(bm + r) * K + c8 * 8);
    }
#pragma unroll
    for (int i = 0; i < 8; i++) {
        int idx = tid + i * 256;
        int r = idx >> 3, c8 = idx & 7;
        CP16(st + 16384u + (uint32_t)((r * 128 + c8 * 16) ^ ((r & 7) << 4)),
             Bb + (size_t)(bn + r) * K + c8 * 8);
    }
    CP_COMMIT();
}

__global__ __launch_bounds__(256, 1)
void hgemm(const __half* __restrict__ A, const __half* __restrict__ B,
           float* __restrict__ C, int N, int K, size_t plA, size_t plB,
           uint32_t wa, uint32_t wb, int NP, float alpha)
{
    extern __shared__ char smem[];
    const uint32_t sb = smem_u32(smem);
    const int tid = threadIdx.x, wid = tid >> 5, lane = tid & 31;
    const int bm = blockIdx.y * BM, bn = blockIdx.x * BN;
    const int wm = (wid >> 2) * 64, wn = (wid & 3) * 64;
    const int CH = K >> 6;
    const int TOT = NP * CH;

    float c[4][8][4];
#pragma unroll
    for (int i = 0; i < 4; i++)
#pragma unroll
        for (int j = 0; j < 8; j++)
#pragma unroll
            for (int q = 0; q < 4; q++) c[i][j][q] = 0.f;

#pragma unroll
    for (int s = 0; s < NSTG - 1; s++)
        hload(sb + (uint32_t)s * STAGEB, A, B, bm, bn, K, plA, plB, wa, wb, s, CH, tid);

    const int a_mrow = lane & 15;
    const int a_kc   = lane >> 4;
    const int b_nrow = (lane & 7) + ((lane >> 4) << 3);
    const int b_kc   = (lane >> 3) & 1;

    uint32_t a[2][4][4], b[2][4][4];

    for (int t = 0; t < TOT; t++) {
        const uint32_t st = sb + (uint32_t)(t % NSTG) * STAGEB;
        CP_WAIT(NSTG - 2);
        __syncthreads();
        if (t + NSTG - 1 < TOT)
            hload(sb + (uint32_t)((t + NSTG - 1) % NSTG) * STAGEB, A, B, bm, bn, K,
                  plA, plB, wa, wb, t + NSTG - 1, CH, tid);
        else
            CP_COMMIT();

        // Prefetch kk=0 fragments
#pragma unroll
        for (int mt = 0; mt < 4; mt++) {
            int r = wm + mt * 16 + a_mrow;
            LDM4(a[0][mt][0], a[0][mt][1], a[0][mt][2], a[0][mt][3],
                 st + (uint32_t)((r * 128 + a_kc * 16) ^ ((r & 7) << 4)));
        }
#pragma unroll
        for (int nt = 0; nt < 4; nt++) {
            int r = wn + nt * 16 + b_nrow;
            LDM4(b[0][nt][0], b[0][nt][1], b[0][nt][2], b[0][nt][3],
                 st + 16384u + (uint32_t)((r * 128 + b_kc * 16) ^ ((r & 7) << 4)));
        }

#pragma unroll
        for (int kk = 0; kk < 4; kk++) {
            const int cur = kk & 1, nxt = cur ^ 1;
            if (kk < 3) {
                const int ch_a = (kk + 1) * 2 + a_kc;
                const int ch_b = (kk + 1) * 2 + b_kc;
#pragma unroll
                for (int mt = 0; mt < 4; mt++) {
                    int r = wm + mt * 16 + a_mrow;
                    LDM4(a[nxt][mt][0], a[nxt][mt][1], a[nxt][mt][2], a[nxt][mt][3],
                         st + (uint32_t)((r * 128 + ch_a * 16) ^ ((r & 7) << 4)));
                }
#pragma unroll
                for (int nt = 0; nt < 4; nt++) {
                    int r = wn + nt * 16 + b_nrow;
                    LDM4(b[nxt][nt][0], b[nxt][nt][1], b[nxt][nt][2], b[nxt][nt][3],
                         st + 16384u + (uint32_t)((r * 128 + ch_b * 16) ^ ((r & 7) << 4)));
                }
            }
#pragma unroll
            for (int mt = 0; mt < 4; mt++)
#pragma unroll
                for (int j = 0; j < 8; j++)
                    MMA16816(c[mt][j][0], c[mt][j][1], c[mt][j][2], c[mt][j][3],
                             a[cur][mt][0], a[cur][mt][1], a[cur][mt][2], a[cur][mt][3],
                             b[cur][j >> 1][(j & 1) * 2], b[cur][j >> 1][(j & 1) * 2 + 1]);
        }
    }

#pragma unroll
    for (int mt = 0; mt < 4; mt++) {
        int row = bm + wm + mt * 16 + (lane >> 2);
#pragma unroll
        for (int j = 0; j < 8; j++) {
            int col = bn + wn + j * 8 + (lane & 3) * 2;
            *(float2*)(C + (size_t)row * N + col) =
                make_float2(alpha * c[mt][j][0], alpha * c[mt][j][1]);
            *(float2*)(C + (size_t)(row + 8) * N + col) =
                make_float2(alpha * c[mt][j][2], alpha * c[mt][j][3]);
        }
    }
}

// ---------------------------------------------------------------------------
__global__ void split2h(const float* __restrict__ a, __half* __restrict__ o,
                        size_t n, float scale)
{
    size_t i = (size_t)blockIdx.x * blockDim.x + threadIdx.x;
    for (; i < n; i += (size_t)gridDim.x * blockDim.x) {
        float x = a[i] * scale;
        __half h = __float2half_rn(x);
        o[i] = h;
        o[n + i] = __float2half_rn(x - __half2float(h));
    }
}

__global__ __launch_bounds__(256)
void topk_kernel(const float* __restrict__ gate, const float* __restrict__ v,
                 __half* __restrict__ ah, __half* __restrict__ am)
{
    __shared__ unsigned s_u[IDIM];
    __shared__ int hist[256];
    __shared__ unsigned s_prefix;
    __shared__ int s_kk, s_adm;

    const int row = blockIdx.x, tid = threadIdx.x;
    const float* grow = gate + (size_t)row * IDIM;
    const float* vrow = v + (size_t)row * IDIM;

    for (int i = tid; i < IDIM; i += 256) {
        unsigned b = __float_as_uint(grow[i]);
        s_u[i] = (b & 0x80000000u) ? ~b : (b | 0x80000000u);
    }
    if (tid == 0) { s_prefix = 0u; s_kk = KSEL; s_adm = 0; }
    __syncthreads();
#pragma unroll
    for (int pass = 0; pass < 4; pass++) {
        const int shift = 24 - 8 * pass;
        hist[tid] = 0;
        __syncthreads();
        const unsigned prefix = s_prefix;
        const unsigned himask = (pass == 0) ? 0u : (0xFFFFFFFFu << (shift + 8));
        for (int i = tid; i < IDIM; i += 256) {
            unsigned u = s_u[i];
            if ((u & himask) == prefix) atomicAdd(&hist[(u >> shift) & 255], 1);
        }
        __syncthreads();
        if (tid == 0) {
            int kk = s_kk, cum = 0, b = 0;
            for (int x = 255; x >= 0; x--) { cum += hist[x]; if (cum >= kk) { b = x; break; } }
            s_kk = kk - (cum - hist[b]);
            s_prefix = prefix | ((unsigned)b << shift);
        }
        __syncthreads();
    }
    const unsigned t = s_prefix;
    const int eq_quota = s_kk;
    __syncthreads();

    for (int i = tid; i < IDIM; i += 256) {
        const unsigned u = s_u[i];
        bool sel = (u > t);
        if (u == t) { if (atomicAdd(&s_adm, 1) < eq_quota) sel = true; }
        float o = 0.f;
        if (sel) {
            unsigned b = (u & 0x80000000u) ? (u & 0x7FFFFFFFu) : ~u;
            float g = __uint_as_float(b);
            o = (g / (1.f + expf(-g))) * vrow[i];
        }
        const size_t idx = (size_t)row * IDIM + i;
        __half h = __float2half_rn(o);
        ah[idx] = h;
        am[idx] = __float2half_rn(o - __half2float(h));
    }
}

// ---------------------------------------------------------------------------
extern "C" void kernel_launch(void* const* d_in, const int* in_sizes, int n_in,
                              void* d_out, int out_size)
{
    const float* x  = (const float*)d_in[0];
    const float* Wg = (const float*)d_in[1];
    const float* Wu = (const float*)d_in[2];
    const float* Wd = (const float*)d_in[3];
    float* out = (float*)d_out;

    float *gate, *vv;
    __half *xs, *wgs, *wus, *wds, *as;
    cudaGetSymbolAddress((void**)&gate, g_gate);
    cudaGetSymbolAddress((void**)&vv, g_v);
    cudaGetSymbolAddress((void**)&xs, g_xs);
    cudaGetSymbolAddress((void**)&wgs, g_wgs);
    cudaGetSymbolAddress((void**)&wus, g_wus);
    cudaGetSymbolAddress((void**)&wds, g_wds);
    cudaGetSymbolAddress((void**)&as, g_as);

    const size_t nx = (size_t)NTOK * HDIM;
    const size_t nw = (size_t)IDIM * HDIM;
    const size_t na = (size_t)NTOK * IDIM;

    cudaFuncSetAttribute(hgemm, cudaFuncAttributeMaxDynamicSharedMemorySize, SMEMSZ);

    split2h<<<2048, 256>>>(x,  xs,  nx, 1.0f);
    split2h<<<2048, 256>>>(Wg, wgs, nw, 32.0f);
    split2h<<<2048, 256>>>(Wu, wus, nw, 32.0f);
    split2h<<<2048, 256>>>(Wd, wds, nw, 32.0f);

    // pair encodings, 4 bits/pair LSB-first
    const uint32_t g3A = 0x100u, g3B = 0x010u;   // (h,h)(h,m)(m,h)
    const uint32_t d2A = 0x00u,  d2B = 0x10u;    // (h,h)(h,m)
    const float alpha = 1.0f / 32.0f;

    // gate = x @ Wg^T (3 pairs, selection-critical)
    hgemm<<<dim3(IDIM / BN, NTOK / BM), 256, SMEMSZ>>>(
        xs, wgs, gate, IDIM, HDIM, nx, nw, g3A, g3B, 3, alpha);
    // v = x @ Wu^T (2 pairs)
    hgemm<<<dim3(IDIM / BN, NTOK / BM), 256, SMEMSZ>>>(
        xs, wus, vv, IDIM, HDIM, nx, nw, d2A, d2B, 2, alpha);
    // top-k + silu*v -> fp16 2-way split activation
    topk_kernel<<<NTOK, 256>>>(gate, vv, as, as + na);
    // out = act @ Wd^T (2 pairs)
    hgemm<<<dim3(HDIM / BN, NTOK / BM), 256, SMEMSZ>>>(
        as, wds, out, HDIM, IDIM, na, nw, d2A, d2B, 2, alpha);
}

// round 9
// speedup vs baseline: 3.7823x; 1.1544x over previous
#include <cuda_runtime.h>
#include <cuda_fp16.h>
#include <cstdint>
#include <cmath>

#define NTOK 8192
#define HDIM 2048
#define IDIM 8192
#define KSEL 2048

__device__ float g_gate[(size_t)NTOK * IDIM];
__device__ float g_v   [(size_t)NTOK * IDIM];
__device__ __half g_xs [2 * (size_t)NTOK * HDIM];
__device__ __half g_wgs[2 * (size_t)IDIM * HDIM];
__device__ __half g_wus[2 * (size_t)IDIM * HDIM];
__device__ __half g_wds[2 * (size_t)HDIM * IDIM];
__device__ __half g_as [2 * (size_t)NTOK * IDIM];

__device__ __forceinline__ uint32_t smem_u32(const void* p) {
    uint32_t a;
    asm("{ .reg .u64 t; cvta.to.shared.u64 t, %1; cvt.u32.u64 %0, t; }" : "=r"(a) : "l"(p));
    return a;
}
#define CP16(d, s)  asm volatile("cp.async.cg.shared.global [%0], [%1], 16;" :: "r"(d), "l"(s) : "memory")
#define CP_COMMIT() asm volatile("cp.async.commit_group;" ::: "memory")
#define CP_WAIT(n)  asm volatile("cp.async.wait_group %0;" :: "n"(n) : "memory")
#define LDM4(r0, r1, r2, r3, a) \
    asm volatile("ldmatrix.sync.aligned.m8n8.x4.shared.b16 {%0,%1,%2,%3}, [%4];" \
                 : "=r"(r0), "=r"(r1), "=r"(r2), "=r"(r3) : "r"(a))
#define MMA16816(c0, c1, c2, c3, a0, a1, a2, a3, b0, b1) \
    asm volatile("mma.sync.aligned.m16n8k16.row.col.f32.f16.f16.f32 " \
                 "{%0,%1,%2,%3},{%4,%5,%6,%7},{%8,%9},{%0,%1,%2,%3};" \
                 : "+f"(c0), "+f"(c1), "+f"(c2), "+f"(c3) \
                 : "r"(a0), "r"(a1), "r"(a2), "r"(a3), "r"(b0), "r"(b1))
#define SWZ(o) ((uint32_t)(o) ^ ((((uint32_t)(o)) >> 3) & 0x70u) ^ 0u)

// ---------------------------------------------------------------------------
// Shared-plane split-fp16 GEMM.
//   C[m][n] = alpha * sum_{p<NP} A_plane[pa_p][m,:] . B_plane[pb_p][n,:]
// All SA A-planes and SB B-planes of each K-chunk live in SMEM simultaneously;
// every pass-pair reuses them (planes hit SMEM once per chunk, not per pair).
// CTA tile 128x256, 256 threads (8 warps 2x4), warp tile 64x64.
// K-chunk 64 (128B rows, XOR swizzle).  Stage = SA*16KB + SB*32KB.
// ---------------------------------------------------------------------------
#define BM 128
#define BN 256

template<int SA, int SB>
__device__ __forceinline__ void hload(uint32_t st,
    const __half* __restrict__ A, const __half* __restrict__ B,
    int bm, int bn, int K, size_t plA, size_t plB, int k0, int tid)
{
#pragma unroll
    for (int p = 0; p < SA; p++) {
        const __half* Ab = A + (size_t)p * plA + k0;
#pragma unroll
        for (int i = 0; i < 4; i++) {
            int idx = tid + i * 256;
            int r = idx >> 3, c8 = idx & 7;
            CP16(st + (uint32_t)p * 16384u + SWZ(r * 128 + c8 * 16),
                 Ab + (size_t)(bm + r) * K + c8 * 8);
        }
    }
#pragma unroll
    for (int q = 0; q < SB; q++) {
        const __half* Bb = B + (size_t)q * plB + k0;
#pragma unroll
        for (int i = 0; i < 8; i++) {
            int idx = tid + i * 256;
            int r = idx >> 3, c8 = idx & 7;
            CP16(st + (uint32_t)(SA * 16384) + (uint32_t)q * 32768u + SWZ(r * 128 + c8 * 16),
                 Bb + (size_t)(bn + r) * K + c8 * 8);
        }
    }
    CP_COMMIT();
}

template<int SA, int SB, int NP, int NSTG, int PA, int PB>
__global__ __launch_bounds__(256, 1)
void hgemm(const __half* __restrict__ A, const __half* __restrict__ B,
           float* __restrict__ C, int N, int K, size_t plA, size_t plB, float alpha)
{
    constexpr int STAGE = SA * 16384 + SB * 32768;
    extern __shared__ char smem[];
    const uint32_t sb = smem_u32(smem);
    const int tid = threadIdx.x, wid = tid >> 5, lane = tid & 31;
    const int bm = blockIdx.y * BM, bn = blockIdx.x * BN;
    const int wm = (wid >> 2) * 64, wn = (wid & 3) * 64;
    const int CH = K >> 6;

    float c[4][8][4];
#pragma unroll
    for (int i = 0; i < 4; i++)
#pragma unroll
        for (int j = 0; j < 8; j++)
#pragma unroll
            for (int q = 0; q < 4; q++) c[i][j][q] = 0.f;

#pragma unroll
    for (int s = 0; s < NSTG - 1; s++)
        hload<SA, SB>(sb + (uint32_t)s * STAGE, A, B, bm, bn, K, plA, plB, s * 64, tid);

    const int a_mrow = lane & 15;
    const int a_kc   = lane >> 4;
    const int b_nrow = (lane & 7) + ((lane >> 4) << 3);
    const int b_kc   = (lane >> 3) & 1;

    for (int t = 0; t < CH; t++) {
        const uint32_t st = sb + (uint32_t)(t % NSTG) * STAGE;
        CP_WAIT(NSTG - 2);
        __syncthreads();
        if (t + NSTG - 1 < CH)
            hload<SA, SB>(sb + (uint32_t)((t + NSTG - 1) % NSTG) * STAGE, A, B,
                          bm, bn, K, plA, plB, (t + NSTG - 1) * 64, tid);
        else
            CP_COMMIT();

#pragma unroll
        for (int kk = 0; kk < 4; kk++) {
            uint32_t a[SA][4][4], b[SB][4][4];
#pragma unroll
            for (int p = 0; p < SA; p++)
#pragma unroll
                for (int mt = 0; mt < 4; mt++) {
                    int r = wm + mt * 16 + a_mrow;
                    int ch = kk * 2 + a_kc;
                    LDM4(a[p][mt][0], a[p][mt][1], a[p][mt][2], a[p][mt][3],
                         st + (uint32_t)p * 16384u + SWZ(r * 128 + ch * 16));
                }
#pragma unroll
            for (int q = 0; q < SB; q++)
#pragma unroll
                for (int nt = 0; nt < 4; nt++) {
                    int r = wn + nt * 16 + b_nrow;
                    int ch = kk * 2 + b_kc;
                    LDM4(b[q][nt][0], b[q][nt][1], b[q][nt][2], b[q][nt][3],
                         st + (uint32_t)(SA * 16384) + (uint32_t)q * 32768u + SWZ(r * 128 + ch * 16));
                }
#pragma unroll
            for (int p = 0; p < NP; p++) {
                constexpr int SHF = 4;
                const int pa = (PA >> (SHF * p)) & 15;
                const int pb = (PB >> (SHF * p)) & 15;
#pragma unroll
                for (int mt = 0; mt < 4; mt++)
#pragma unroll
                    for (int j = 0; j < 8; j++)
                        MMA16816(c[mt][j][0], c[mt][j][1], c[mt][j][2], c[mt][j][3],
                                 a[pa][mt][0], a[pa][mt][1], a[pa][mt][2], a[pa][mt][3],
                                 b[pb][j >> 1][(j & 1) * 2], b[pb][j >> 1][(j & 1) * 2 + 1]);
            }
        }
    }

#pragma unroll
    for (int mt = 0; mt < 4; mt++) {
        int row = bm + wm + mt * 16 + (lane >> 2);
#pragma unroll
        for (int j = 0; j < 8; j++) {
            int col = bn + wn + j * 8 + (lane & 3) * 2;
            *(float2*)(C + (size_t)row * N + col) =
                make_float2(alpha * c[mt][j][0], alpha * c[mt][j][1]);
            *(float2*)(C + (size_t)(row + 8) * N + col) =
                make_float2(alpha * c[mt][j][2], alpha * c[mt][j][3]);
        }
    }
}

// ---------------------------------------------------------------------------
// fp16 2-way split, float4-vectorized (scale is a power of 2; undone by alpha)
__global__ void split2h(const float4* __restrict__ a, __half* __restrict__ o,
                        size_t n, float scale)     // n = element count (mult of 4)
{
    const size_t n4 = n >> 2;
    size_t i = (size_t)blockIdx.x * blockDim.x + threadIdx.x;
    for (; i < n4; i += (size_t)gridDim.x * blockDim.x) {
        float4 x = a[i];
        x.x *= scale; x.y *= scale; x.z *= scale; x.w *= scale;
        __half h0 = __float2half_rn(x.x), h1 = __float2half_rn(x.y);
        __half h2 = __float2half_rn(x.z), h3 = __float2half_rn(x.w);
        __half2 hh0 = __halves2half2(h0, h1), hh1 = __halves2half2(h2, h3);
        *(__half2*)(o + 4 * i)     = hh0;
        *(__half2*)(o + 4 * i + 2) = hh1;
        __half2 mm0 = __halves2half2(__float2half_rn(x.x - __half2float(h0)),
                                     __float2half_rn(x.y - __half2float(h1)));
        __half2 mm1 = __halves2half2(__float2half_rn(x.z - __half2float(h2)),
                                     __float2half_rn(x.w - __half2float(h3)));
        *(__half2*)(o + n + 4 * i)     = mm0;
        *(__half2*)(o + n + 4 * i + 2) = mm1;
    }
}

// Per-token exact top-K (4-pass radix select) + silu(gate)*v -> fp16 2-split
__global__ __launch_bounds__(256)
void topk_kernel(const float* __restrict__ gate, const float* __restrict__ v,
                 __half* __restrict__ ah, __half* __restrict__ am)
{
    __shared__ unsigned s_u[IDIM];
    __shared__ int hist[256];
    __shared__ unsigned s_prefix;
    __shared__ int s_kk, s_adm;

    const int row = blockIdx.x, tid = threadIdx.x;
    const float* grow = gate + (size_t)row * IDIM;
    const float* vrow = v + (size_t)row * IDIM;

    for (int i = tid * 4; i < IDIM; i += 1024) {
        float4 g4 = *(const float4*)(grow + i);
#pragma unroll
        for (int q = 0; q < 4; q++) {
            unsigned b = __float_as_uint(((const float*)&g4)[q]);
            s_u[i + q] = (b & 0x80000000u) ? ~b : (b | 0x80000000u);
        }
    }
    if (tid == 0) { s_prefix = 0u; s_kk = KSEL; s_adm = 0; }
    __syncthreads();
#pragma unroll
    for (int pass = 0; pass < 4; pass++) {
        const int shift = 24 - 8 * pass;
        hist[tid] = 0;
        __syncthreads();
        const unsigned prefix = s_prefix;
        const unsigned himask = (pass == 0) ? 0u : (0xFFFFFFFFu << (shift + 8));
        for (int i = tid; i < IDIM; i += 256) {
            unsigned u = s_u[i];
            if ((u & himask) == prefix) atomicAdd(&hist[(u >> shift) & 255], 1);
        }
        __syncthreads();
        if (tid == 0) {
            int kk = s_kk, cum = 0, b = 0;
            for (int x = 255; x >= 0; x--) { cum += hist[x]; if (cum >= kk) { b = x; break; } }
            s_kk = kk - (cum - hist[b]);
            s_prefix = prefix | ((unsigned)b << shift);
        }
        __syncthreads();
    }
    const unsigned t = s_prefix;
    const int eq_quota = s_kk;
    __syncthreads();

    for (int i = tid * 4; i < IDIM; i += 1024) {
        float4 v4 = *(const float4*)(vrow + i);
        __half hs[4], ms[4];
#pragma unroll
        for (int q = 0; q < 4; q++) {
            const unsigned u = s_u[i + q];
            bool sel = (u > t);
            if (u == t) { if (atomicAdd(&s_adm, 1) < eq_quota) sel = true; }
            float o = 0.f;
            if (sel) {
                unsigned b = (u & 0x80000000u) ? (u & 0x7FFFFFFFu) : ~u;
                float g = __uint_as_float(b);
                o = (g / (1.f + expf(-g))) * ((const float*)&v4)[q];
            }
            hs[q] = __float2half_rn(o);
            ms[q] = __float2half_rn(o - __half2float(hs[q]));
        }
        const size_t idx = (size_t)row * IDIM + i;
        *(__half2*)(ah + idx)     = __halves2half2(hs[0], hs[1]);
        *(__half2*)(ah + idx + 2) = __halves2half2(hs[2], hs[3]);
        *(__half2*)(am + idx)     = __halves2half2(ms[0], ms[1]);
        *(__half2*)(am + idx + 2) = __halves2half2(ms[2], ms[3]);
    }
}

// ---------------------------------------------------------------------------
extern "C" void kernel_launch(void* const* d_in, const int* in_sizes, int n_in,
                              void* d_out, int out_size)
{
    const float* x  = (const float*)d_in[0];
    const float* Wg = (const float*)d_in[1];
    const float* Wu = (const float*)d_in[2];
    const float* Wd = (const float*)d_in[3];
    float* out = (float*)d_out;

    float *gate, *vv;
    __half *xs, *wgs, *wus, *wds, *as;
    cudaGetSymbolAddress((void**)&gate, g_gate);
    cudaGetSymbolAddress((void**)&vv, g_v);
    cudaGetSymbolAddress((void**)&xs, g_xs);
    cudaGetSymbolAddress((void**)&wgs, g_wgs);
    cudaGetSymbolAddress((void**)&wus, g_wus);
    cudaGetSymbolAddress((void**)&wds, g_wds);
    cudaGetSymbolAddress((void**)&as, g_as);

    const size_t nx = (size_t)NTOK * HDIM;
    const size_t nw = (size_t)IDIM * HDIM;
    const size_t na = (size_t)NTOK * IDIM;
    const float alpha = 1.0f / 32.0f;

    // gate: SA=2,SB=2, pairs (0,0)(0,1)(1,0); stage 96KB, 2 stages = 192KB
    auto kg = hgemm<2, 2, 3, 2, 0x100, 0x010>;
    // up/down: SA=2,SB=1, pairs (0,0)(1,0); stage 64KB, 3 stages = 192KB
    auto ks = hgemm<2, 1, 2, 3, 0x10, 0x00>;
    cudaFuncSetAttribute(kg, cudaFuncAttributeMaxDynamicSharedMemorySize, 196608);
    cudaFuncSetAttribute(ks, cudaFuncAttributeMaxDynamicSharedMemorySize, 196608);

    split2h<<<2048, 256>>>((const float4*)x,  xs,  nx, 1.0f);
    split2h<<<2048, 256>>>((const float4*)Wg, wgs, nw, 32.0f);
    split2h<<<2048, 256>>>((const float4*)Wu, wus, nw, 32.0f);
    split2h<<<2048, 256>>>((const float4*)Wd, wds, nw, 32.0f);

    // gate = x @ Wg^T : M=8192, N=8192, K=2048 (3 pairs, selection-critical)
    kg<<<dim3(IDIM / BN, NTOK / BM), 256, 196608>>>(
        xs, wgs, gate, IDIM, HDIM, nx, nw, alpha);
    // v = (xh+xm) @ Wu_h^T (2 pairs, shared B plane)
    ks<<<dim3(IDIM / BN, NTOK / BM), 256, 196608>>>(
        xs, wus, vv, IDIM, HDIM, nx, nw, alpha);
    // top-k + silu*v -> fp16 2-way split activation
    topk_kernel<<<NTOK, 256>>>(gate, vv, as, as + na);
    // out = (act_h+act_m) @ Wd_h^T : M=8192, N=2048, K=8192
    ks<<<dim3(HDIM / BN, NTOK / BM), 256, 196608>>>(
        as, wds, out, HDIM, IDIM, na, nw, alpha);
}